// round 12
// baseline (speedup 1.0000x reference)
#include <cuda_runtime.h>

#define H 512
#define W 512
#define CH 3
#define NB 16               // batches
#define NS 48               // 16 batches * 3 channels
#define SYS (H*W)
#define NTOT (NS*SYS)
#define BROW (NB*H)         // 8192 batch-rows
#define WCN (511*512)
#define WRN (512*511)
#define WPTOT (NB*SYS)      // padded row-weight elements
#define MAXIT 100
#define EPS_F 158.32966f    // (1e-6 * 16*3*512*512)^2
#define TPB 384             // 3 groups of 128 threads (one per channel)
#define MAXMEM 64           // max member blocks per batch

__device__ float g_r[NTOT];
__device__ float g_pbuf[2][NTOT];
__device__ float g_wrp[WPTOT];       // row weights, padded stride 512 (col 511 = 0)
// per-block partial dots: [slot][system][member]  (plain stores, no atomics)
__device__ float g_prr[3][NS][MAXMEM];
__device__ float g_ppap[3][NS][MAXMEM];
// global convergence machinery
__device__ float g_batrr[MAXIT][NB];
__device__ unsigned int g_cnt[MAXIT];
__device__ volatile int g_verdict[MAXIT];   // 0=pending 1=continue 2=stop
// barriers
__device__ unsigned int g_bar_arrive;
__device__ volatile unsigned int g_bar_phase;
__device__ unsigned int g_barr[NB*32];
__device__ volatile unsigned int g_bph[NB*32];

__device__ __forceinline__ float4 ld4(const float* p) { return *reinterpret_cast<const float4*>(p); }
__device__ __forceinline__ void st4(float* p, float4 v) { *reinterpret_cast<float4*>(p) = v; }

__device__ __forceinline__ float nan0(float v) {
    if (isnan(v)) return 0.0f;
    if (isinf(v)) return v > 0.f ? 3.402823466e38f : -3.402823466e38f;
    return v;
}

__device__ __forceinline__ float psum(const float* a, int n) {
    float t = 0.f;
    for (int m = 0; m < n; m++) t += a[m];
    return t;
}

__device__ __forceinline__ void grid_barrier(int G, unsigned int &gen) {
    __syncthreads();
    if (threadIdx.x == 0) {
        __threadfence();
        unsigned int t = atomicAdd(&g_bar_arrive, 1u);
        if (t == (unsigned int)(G - 1)) {
            g_bar_arrive = 0;
            __threadfence();
            g_bar_phase = gen + 1u;
        } else {
            while (g_bar_phase == gen) { __nanosleep(64); }
        }
        gen++;
        __threadfence();
    }
    __syncthreads();
}

// Per-batch barrier over this block's 1-2 batches. Arrive-all-then-wait.
__device__ __forceinline__ void bat_barrier(int bA, int cA, int bB, int cB, bool two,
                                            unsigned int &ga, unsigned int &gb)
{
    __syncthreads();
    if (threadIdx.x == 0) {
        __threadfence();
        unsigned int t = atomicAdd(&g_barr[bA * 32], 1u);
        if (t == (unsigned int)(cA - 1)) { g_barr[bA*32] = 0; __threadfence(); g_bph[bA*32] = ga + 1u; }
        if (two) {
            unsigned int u = atomicAdd(&g_barr[bB * 32], 1u);
            if (u == (unsigned int)(cB - 1)) { g_barr[bB*32] = 0; __threadfence(); g_bph[bB*32] = gb + 1u; }
        }
        while (g_bph[bA*32] == ga) __nanosleep(32);
        ga++;
        if (two) { while (g_bph[bB*32] == gb) __nanosleep(32); gb++; }
        __threadfence();
    }
    __syncthreads();
}

template<bool COMBINE>
__device__ __forceinline__ float4 ldz(const float* __restrict__ z,
                                      const float* __restrict__ pb,
                                      float coef, int e)
{
    float4 v = ld4(z + e);
    if (COMBINE) {
        float4 q = ld4(pb + e);
        v.x = fmaf(coef, q.x, v.x); v.y = fmaf(coef, q.y, v.y);
        v.z = fmaf(coef, q.z, v.z); v.w = fmaf(coef, q.w, v.w);
    }
    return v;
}

// One stencil row; branchless boundaries (invalid-side weights/z pre-zeroed).
template<int PASS, bool COMBINE>
__device__ __forceinline__ void do_row(
    float4 zu, float4 zc, float4 zd,
    float4 wcu, float4 wcd, float4 wv,
    const float* __restrict__ zsrc, const float* __restrict__ pb, float coef,
    const float* __restrict__ wrb,
    float* __restrict__ o1, float* __restrict__ o2,
    int gi, int lane, int j0, float &acc)
{
    float wl = __shfl_up_sync(0xffffffffu, wv.w, 1);
    float xl = __shfl_up_sync(0xffffffffu, zc.w, 1);
    float xr = __shfl_down_sync(0xffffffffu, zc.x, 1);
    if (lane == 0) {
        if (j0 > 0) {
            xl = zsrc[gi - 1];
            if (COMBINE) xl = fmaf(coef, pb[gi - 1], xl);
            wl = wrb[gi - 1];
        } else wl = 0.f;
    }
    if (lane == 31 && j0 + 4 < W) {
        xr = zsrc[gi + 4];
        if (COMBINE) xr = fmaf(coef, pb[gi + 4], xr);
    }

    float y0 = zc.x, y1 = zc.y, y2 = zc.z, y3 = zc.w;
    y0 += wcu.x * (zc.x - zu.x); y1 += wcu.y * (zc.y - zu.y);
    y2 += wcu.z * (zc.z - zu.z); y3 += wcu.w * (zc.w - zu.w);
    y0 += wcd.x * (zc.x - zd.x); y1 += wcd.y * (zc.y - zd.y);
    y2 += wcd.z * (zc.z - zd.z); y3 += wcd.w * (zc.w - zd.w);
    y0 += wv.x * (zc.x - zc.y);
    y1 += wv.x * (zc.y - zc.x) + wv.y * (zc.y - zc.z);
    y2 += wv.y * (zc.z - zc.y) + wv.z * (zc.z - zc.w);
    y3 += wv.z * (zc.w - zc.z);
    y0 += wl * (zc.x - xl);
    y3 += wv.w * (zc.w - xr);            // wv.w==0 at right edge (padded)

    if (PASS == 0) {
        float4 rn = make_float4(zc.x - y0, zc.y - y1, zc.z - y2, zc.w - y3);
        st4(o1 + gi, rn);
        st4(o2 + gi, zc);
        acc += rn.x * rn.x + rn.y * rn.y + rn.z * rn.z + rn.w * rn.w;
    } else if (PASS == 1) {
        st4(o1 + gi, zc);
        acc += zc.x * y0 + zc.y * y1 + zc.z * y2 + zc.w * y3;
    } else {
        float4 rv = ld4(o1 + gi);
        float4 xv = ld4(o2 + gi);
        rv.x -= coef * y0; rv.y -= coef * y1;
        rv.z -= coef * y2; rv.w -= coef * y3;
        xv.x = fmaf(coef, zc.x, xv.x); xv.y = fmaf(coef, zc.y, xv.y);
        xv.z = fmaf(coef, zc.z, xv.z); xv.w = fmaf(coef, zc.w, xv.w);
        st4(o1 + gi, rv);
        st4(o2 + gi, xv);
        acc += rv.x * rv.x + rv.y * rv.y + rv.z * rv.z + rv.w * rv.w;
    }
}

// Register-rolling sweep over rows [i0,i1), unrolled by 2 for MLP.
template<int PASS, bool COMBINE>
__device__ __forceinline__ void sweep_seg(
    const float* __restrict__ zsrc, const float* __restrict__ pb, float coef,
    const float* __restrict__ wcb, const float* __restrict__ wrb,
    float* __restrict__ o1, float* __restrict__ o2,
    int i0, int i1, int j0, int lane, float &acc)
{
    const float4 Z0 = make_float4(0.f, 0.f, 0.f, 0.f);
    float4 zu = Z0, zc, zd, ze;

    if (i0 > 0) zu = ldz<COMBINE>(zsrc, pb, coef, (i0 - 1) * W + j0);
    zc = ldz<COMBINE>(zsrc, pb, coef, i0 * W + j0);

    int i = i0;
    int gi = i0 * W + j0;
    for (; i + 2 <= i1; i += 2, gi += 2 * W) {
        const bool up  = (i > 0);
        const bool dn2 = (i + 2 < H);
        zd = ldz<COMBINE>(zsrc, pb, coef, gi + W);
        ze = dn2 ? ldz<COMBINE>(zsrc, pb, coef, gi + 2 * W) : Z0;
        float4 wv  = ld4(wrb + gi);
        float4 wv2 = ld4(wrb + gi + W);
        float4 wcu = up  ? ld4(wcb + (i - 1) * W + j0) : Z0;
        float4 wcm = ld4(wcb + i * W + j0);
        float4 wcd = dn2 ? ld4(wcb + (i + 1) * W + j0) : Z0;

        do_row<PASS, COMBINE>(zu, zc, zd, wcu, wcm, wv,
                              zsrc, pb, coef, wrb, o1, o2, gi, lane, j0, acc);
        do_row<PASS, COMBINE>(zc, zd, ze, wcm, wcd, wv2,
                              zsrc, pb, coef, wrb, o1, o2, gi + W, lane, j0, acc);
        zu = zd; zc = ze;
    }
    if (i < i1) {
        const bool up = (i > 0), dn = (i < H - 1);
        zd = dn ? ldz<COMBINE>(zsrc, pb, coef, gi + W) : Z0;
        float4 wv  = ld4(wrb + gi);
        float4 wcu = up ? ld4(wcb + (i - 1) * W + j0) : Z0;
        float4 wcd = dn ? ld4(wcb + i * W + j0) : Z0;
        do_row<PASS, COMBINE>(zu, zc, zd, wcu, wcd, wv,
                              zsrc, pb, coef, wrb, o1, o2, gi, lane, j0, acc);
    }
}

// Per-group (128-thread) reduce; one PLAIN STORE per group per covered batch.
__device__ __forceinline__ void reduce_grp_store(float a0, float a1, int grp,
                                                 float* d0, float* d1)
{
    __shared__ float sm[2][3][4];
    #pragma unroll
    for (int o = 16; o; o >>= 1) {
        a0 += __shfl_down_sync(0xffffffffu, a0, o);
        a1 += __shfl_down_sync(0xffffffffu, a1, o);
    }
    int wg = (threadIdx.x >> 5) & 3;
    int lane = threadIdx.x & 31;
    if (lane == 0) { sm[0][grp][wg] = a0; sm[1][grp][wg] = a1; }
    __syncthreads();
    if (wg == 0 && lane == 0) {
        *d0 = sm[0][grp][0] + sm[0][grp][1] + sm[0][grp][2] + sm[0][grp][3];
        if (d1) *d1 = sm[1][grp][0] + sm[1][grp][1] + sm[1][grp][2] + sm[1][grp][3];
    }
    __syncthreads();
}

// Iterate batch-aligned segments of batch-row range [q0,q1): calls f(b, i0, i1).
template<typename F>
__device__ __forceinline__ void for_segs(int q0, int q1, F f)
{
    int a = q0;
    while (a < q1) {
        int b = a >> 9;
        int send = q1 < ((b + 1) << 9) ? q1 : ((b + 1) << 9);
        f(b, a & 511, (a & 511) + (send - a));
        a = send;
    }
}

// Owner posts batch rr (3 channels) for iteration k; 16th writes verdict.
__device__ __forceinline__ void post_bat(int k, int b, int cnt, int slot)
{
    float tot = 0.f;
    for (int c = 0; c < CH; c++) tot += psum(g_prr[slot][b * CH + c], cnt);
    g_batrr[k][b] = tot;
    __threadfence();
    unsigned int got = atomicAdd(&g_cnt[k], 1u);
    if (got == (unsigned int)(NB - 1)) {
        __threadfence();
        float gt = 0.f;
        volatile float* vr = (volatile float*)g_batrr[k];
        for (int t = 0; t < NB; t++) gt += vr[t];
        g_verdict[k] = (gt < EPS_F) ? 2 : 1;
    }
}

extern "C" __global__ void __launch_bounds__(TPB, 3)
cg_persistent(const float* __restrict__ Bin, const float* __restrict__ wc,
              const float* __restrict__ wr, float* __restrict__ x, int G)
{
    unsigned int gen = g_bar_phase;   // survives graph replays
    const int bi = blockIdx.x;
    const int r0 = (int)(((long long)bi * BROW) / G);
    const int r1 = (int)(((long long)(bi + 1) * BROW) / G);
    const int b0 = r0 >> 9;
    const bool has2 = ((r1 - 1) >> 9) > b0;
    // membership within batch(es)
    const int fb0 = (int)((((long long)b0 * H + 1) * G - 1) / BROW);
    const int lb0 = (int)((((long long)(b0 + 1) * H) * G - 1) / BROW);
    const int cnt0 = lb0 - fb0 + 1;
    const int mi0 = bi - fb0;
    int cnt1 = 0, mi1 = 0;
    if (has2) {
        int fb1 = (int)((((long long)(b0 + 1) * H + 1) * G - 1) / BROW);
        int lb1 = (int)((((long long)(b0 + 2) * H) * G - 1) / BROW);
        cnt1 = lb1 - fb1 + 1;
        mi1 = bi - fb1;
    }
    unsigned int ga = g_bph[b0 * 32];
    unsigned int gb = has2 ? g_bph[(b0 + 1) * 32] : 0u;

    const int grp = threadIdx.x >> 7;           // channel 0..2
    const int j0 = (threadIdx.x & 127) << 2;
    const int lane = threadIdx.x & 31;

    __shared__ float s_coef[2][3];              // [batch-idx][channel]
    __shared__ int s_v;

    // Phase Z: zero verdict machinery; repack row weights (padded, zero col 511)
    if (bi == 0) {
        for (int t = threadIdx.x; t < MAXIT; t += TPB) {
            g_cnt[t] = 0u;
            g_verdict[t] = 0;
        }
    }
    for (int t = bi * TPB + threadIdx.x; t < WPTOT; t += G * TPB) {
        int b = t >> 18;
        int rem = t & (SYS - 1);
        int i = rem >> 9, j = rem & 511;
        g_wrp[t] = (j < 511) ? wr[b * WRN + i * 511 + j] : 0.f;
    }
    grid_barrier(G, gen);   // single global barrier per launch

    // Setup: x = B; r = B - A*B; rr0 partials -> slot 0
    {
        float a0 = 0.f, a1 = 0.f;
        for_segs(r0, r1, [&](int b, int i0, int i1) {
            int s = b * CH + grp;
            float acc = 0.f;
            sweep_seg<0, false>(Bin + s * SYS, (const float*)0, 0.f,
                                wc + b * WCN, g_wrp + b * SYS,
                                g_r + s * SYS, x + s * SYS, i0, i1, j0, lane, acc);
            if (b == b0) a0 += acc; else a1 += acc;
        });
        reduce_grp_store(a0, a1, grp, &g_prr[0][b0 * CH + grp][mi0],
                         has2 ? &g_prr[0][(b0 + 1) * CH + grp][mi1] : (float*)0);
    }
    bat_barrier(b0, cnt0, b0 + 1, cnt1, has2, ga, gb);

    for (int k = 0; k < MAXIT; ++k) {
        const int cur = k % 3, prv = (k + 2) % 3, nxt = (k + 1) % 3;
        float* __restrict__ pnew = g_pbuf[k & 1];
        const float* __restrict__ pold = g_pbuf[(k + 1) & 1];

        // beta into smem (k>0); 6 threads, one per (batch-idx, channel)
        if (k > 0) {
            if (threadIdx.x < 6) {
                int bidx = threadIdx.x / 3, gch = threadIdx.x % 3;
                if (bidx == 0 || has2) {
                    int cnt = bidx ? cnt1 : cnt0;
                    int s = (b0 + bidx) * CH + gch;
                    s_coef[bidx][gch] =
                        nan0(psum(g_prr[cur][s], cnt) / psum(g_prr[prv][s], cnt));
                }
            }
            __syncthreads();
        }

        // ---- Pass 1 (speculative w.r.t. verdict): p = r + beta*pold; pAp partials
        {
            float a0 = 0.f, a1 = 0.f;
            for_segs(r0, r1, [&](int b, int i0, int i1) {
                int s = b * CH + grp;
                float acc = 0.f;
                if (k == 0) {
                    sweep_seg<1, false>(g_r + s * SYS, (const float*)0, 0.f,
                                        wc + b * WCN, g_wrp + b * SYS,
                                        pnew + s * SYS, (float*)0, i0, i1, j0, lane, acc);
                } else {
                    float beta = s_coef[b == b0 ? 0 : 1][grp];
                    sweep_seg<1, true>(g_r + s * SYS, pold + s * SYS, beta,
                                       wc + b * WCN, g_wrp + b * SYS,
                                       pnew + s * SYS, (float*)0, i0, i1, j0, lane, acc);
                }
                if (b == b0) a0 += acc; else a1 += acc;
            });
            reduce_grp_store(a0, a1, grp, &g_ppap[cur][b0 * CH + grp][mi0],
                             has2 ? &g_ppap[cur][(b0 + 1) * CH + grp][mi1] : (float*)0);
        }
        bat_barrier(b0, cnt0, b0 + 1, cnt1, has2, ga, gb);

        // ---- Global verdict for iteration k-1 (rendezvous hidden behind pass1)
        if (k > 0) {
            if (threadIdx.x == 0) {
                int v;
                while ((v = g_verdict[k - 1]) == 0) __nanosleep(64);
                s_v = v;
            }
            __syncthreads();
            if (s_v == 2) break;   // x holds x_k; p_k computed (matches reference)
        }

        // alpha into smem
        if (threadIdx.x < 6) {
            int bidx = threadIdx.x / 3, gch = threadIdx.x % 3;
            if (bidx == 0 || has2) {
                int cnt = bidx ? cnt1 : cnt0;
                int s = (b0 + bidx) * CH + gch;
                s_coef[bidx][gch] =
                    nan0(psum(g_prr[cur][s], cnt) / psum(g_ppap[cur][s], cnt));
            }
        }
        __syncthreads();

        // ---- Pass 2: recompute Ap; r -= a*Ap; x += a*p; rr partials -> slot nxt
        {
            float a0 = 0.f, a1 = 0.f;
            for_segs(r0, r1, [&](int b, int i0, int i1) {
                int s = b * CH + grp;
                float alpha = s_coef[b == b0 ? 0 : 1][grp];
                float acc = 0.f;
                sweep_seg<2, false>(pnew + s * SYS, (const float*)0, alpha,
                                    wc + b * WCN, g_wrp + b * SYS,
                                    g_r + s * SYS, x + s * SYS, i0, i1, j0, lane, acc);
                if (b == b0) a0 += acc; else a1 += acc;
            });
            reduce_grp_store(a0, a1, grp, &g_prr[nxt][b0 * CH + grp][mi0],
                             has2 ? &g_prr[nxt][(b0 + 1) * CH + grp][mi1] : (float*)0);
        }
        bat_barrier(b0, cnt0, b0 + 1, cnt1, has2, ga, gb);

        // ---- Owners post batch rr_{k+1}; 16th contributor writes verdict[k]
        if (threadIdx.x == 0) {
            if (mi0 == 0) post_bat(k, b0, cnt0, nxt);
            if (has2 && mi1 == 0) post_bat(k, b0 + 1, cnt1, nxt);
        }
    }
}

extern "C" void kernel_launch(void* const* d_in, const int* in_sizes, int n_in,
                              void* d_out, int out_size)
{
    static int G = 0;
    if (G == 0) {
        int dev = 0;
        cudaGetDevice(&dev);
        int sms = 0;
        cudaDeviceGetAttribute(&sms, cudaDevAttrMultiProcessorCount, dev);
        int occ = 0;
        cudaOccupancyMaxActiveBlocksPerMultiprocessor(&occ, cg_persistent, TPB, 0);
        if (occ < 1) occ = 1;
        G = sms * occ;
        if (G > 960) G = 960;       // MAXMEM bound (<= 61 members/batch)
        if (G > BROW) G = BROW;
    }
    cg_persistent<<<G, TPB>>>((const float*)d_in[0], (const float*)d_in[1],
                              (const float*)d_in[2], (float*)d_out, G);
}

// round 13
// speedup vs baseline: 1.0837x; 1.0837x over previous
#include <cuda_runtime.h>

#define H 512
#define W 512
#define CH 3
#define NB 16               // batches
#define NS 48               // 16 batches * 3 channels
#define SYS (H*W)
#define NTOT (NS*SYS)
#define BROW (NB*H)         // 8192 batch-rows
#define WCN (511*512)
#define WRN (512*511)
#define WPTOT (NB*SYS)      // padded row-weight elements
#define MAXIT 100
#define EPS_F 158.32966f    // (1e-6 * 16*3*512*512)^2
#define TPB 384             // 3 groups of 128 threads (one per channel)

__device__ float g_r[NTOT];
__device__ float g_pbuf[3][NTOT];    // TRIPLE ring: p_{k} lives 3 iterations
__device__ float g_wrp[WPTOT];       // row weights, padded stride 512 (col 511 = 0)
__device__ float g_pAp[3][NS*8];
__device__ float g_rr[3][NS*8];
__device__ unsigned int g_bar_arrive;
__device__ volatile unsigned int g_bar_phase;

__device__ __forceinline__ float4 ld4(const float* p) { return *reinterpret_cast<const float4*>(p); }
__device__ __forceinline__ void st4(float* p, float4 v) { *reinterpret_cast<float4*>(p) = v; }

__device__ __forceinline__ float nan0(float v) {
    if (isnan(v)) return 0.0f;
    if (isinf(v)) return v > 0.f ? 3.402823466e38f : -3.402823466e38f;
    return v;
}

__device__ __forceinline__ void grid_barrier(int G, unsigned int &gen) {
    __syncthreads();
    if (threadIdx.x == 0) {
        __threadfence();
        unsigned int t = atomicAdd(&g_bar_arrive, 1u);
        if (t == (unsigned int)(G - 1)) {
            g_bar_arrive = 0;
            __threadfence();
            g_bar_phase = gen + 1u;
        } else {
            while (g_bar_phase == gen) { __nanosleep(64); }
        }
        gen++;
        __threadfence();
    }
    __syncthreads();
}

template<bool COMBINE>
__device__ __forceinline__ float4 ldz(const float* __restrict__ z,
                                      const float* __restrict__ pb,
                                      float coef, int e)
{
    float4 v = ld4(z + e);
    if (COMBINE) {
        float4 q = ld4(pb + e);
        v.x = fmaf(coef, q.x, v.x); v.y = fmaf(coef, q.y, v.y);
        v.z = fmaf(coef, q.z, v.z); v.w = fmaf(coef, q.w, v.w);
    }
    return v;
}

// One stencil row; branchless boundaries (invalid-side weights/z pre-zeroed).
// PASS 0: setup  (o1<-r, o2<-x=z, acc += |r|^2)
// PASS 1: p-build (o1<-z=p, acc += p.Ap)
// PASS 2: r-update only         (o1 -= coef*y, acc += |r|^2)
// PASS 3: r-update + PAIRED x   (also o2 += aprev*pprev + coef*z)
template<int PASS, bool COMBINE>
__device__ __forceinline__ void do_row(
    float4 zu, float4 zc, float4 zd,
    float4 wcu, float4 wcd, float4 wv,
    const float* __restrict__ zsrc, const float* __restrict__ pb, float coef,
    const float* __restrict__ wrb,
    float* __restrict__ o1, float* __restrict__ o2,
    const float* __restrict__ pprev, float aprev,
    int gi, int lane, int j0, float &acc)
{
    float wl = __shfl_up_sync(0xffffffffu, wv.w, 1);
    float xl = __shfl_up_sync(0xffffffffu, zc.w, 1);
    float xr = __shfl_down_sync(0xffffffffu, zc.x, 1);
    if (lane == 0) {
        if (j0 > 0) {
            xl = zsrc[gi - 1];
            if (COMBINE) xl = fmaf(coef, pb[gi - 1], xl);
            wl = wrb[gi - 1];
        } else wl = 0.f;
    }
    if (lane == 31 && j0 + 4 < W) {
        xr = zsrc[gi + 4];
        if (COMBINE) xr = fmaf(coef, pb[gi + 4], xr);
    }

    float y0 = zc.x, y1 = zc.y, y2 = zc.z, y3 = zc.w;
    y0 += wcu.x * (zc.x - zu.x); y1 += wcu.y * (zc.y - zu.y);
    y2 += wcu.z * (zc.z - zu.z); y3 += wcu.w * (zc.w - zu.w);
    y0 += wcd.x * (zc.x - zd.x); y1 += wcd.y * (zc.y - zd.y);
    y2 += wcd.z * (zc.z - zd.z); y3 += wcd.w * (zc.w - zd.w);
    y0 += wv.x * (zc.x - zc.y);
    y1 += wv.x * (zc.y - zc.x) + wv.y * (zc.y - zc.z);
    y2 += wv.y * (zc.z - zc.y) + wv.z * (zc.z - zc.w);
    y3 += wv.z * (zc.w - zc.z);
    y0 += wl * (zc.x - xl);
    y3 += wv.w * (zc.w - xr);            // wv.w==0 at right edge (padded)

    if (PASS == 0) {
        float4 rn = make_float4(zc.x - y0, zc.y - y1, zc.z - y2, zc.w - y3);
        st4(o1 + gi, rn);
        st4(o2 + gi, zc);
        acc += rn.x * rn.x + rn.y * rn.y + rn.z * rn.z + rn.w * rn.w;
    } else if (PASS == 1) {
        st4(o1 + gi, zc);
        acc += zc.x * y0 + zc.y * y1 + zc.z * y2 + zc.w * y3;
    } else {
        float4 rv = ld4(o1 + gi);
        rv.x -= coef * y0; rv.y -= coef * y1;
        rv.z -= coef * y2; rv.w -= coef * y3;
        st4(o1 + gi, rv);
        if (PASS == 3) {
            float4 xv = ld4(o2 + gi);
            float4 pp = ld4(pprev + gi);
            xv.x += aprev * pp.x + coef * zc.x;
            xv.y += aprev * pp.y + coef * zc.y;
            xv.z += aprev * pp.z + coef * zc.z;
            xv.w += aprev * pp.w + coef * zc.w;
            st4(o2 + gi, xv);
        }
        acc += rv.x * rv.x + rv.y * rv.y + rv.z * rv.z + rv.w * rv.w;
    }
}

// Register-rolling sweep over rows [i0,i1), unrolled by 2 for MLP.
template<int PASS, bool COMBINE>
__device__ __forceinline__ void sweep_seg(
    const float* __restrict__ zsrc, const float* __restrict__ pb, float coef,
    const float* __restrict__ wcb, const float* __restrict__ wrb,
    float* __restrict__ o1, float* __restrict__ o2,
    const float* __restrict__ pprev, float aprev,
    int i0, int i1, int j0, int lane, float &acc)
{
    const float4 Z0 = make_float4(0.f, 0.f, 0.f, 0.f);
    float4 zu = Z0, zc, zd, ze;

    if (i0 > 0) zu = ldz<COMBINE>(zsrc, pb, coef, (i0 - 1) * W + j0);
    zc = ldz<COMBINE>(zsrc, pb, coef, i0 * W + j0);

    int i = i0;
    int gi = i0 * W + j0;
    for (; i + 2 <= i1; i += 2, gi += 2 * W) {
        const bool up  = (i > 0);
        const bool dn2 = (i + 2 < H);
        zd = ldz<COMBINE>(zsrc, pb, coef, gi + W);
        ze = dn2 ? ldz<COMBINE>(zsrc, pb, coef, gi + 2 * W) : Z0;
        float4 wv  = ld4(wrb + gi);
        float4 wv2 = ld4(wrb + gi + W);
        float4 wcu = up  ? ld4(wcb + (i - 1) * W + j0) : Z0;
        float4 wcm = ld4(wcb + i * W + j0);
        float4 wcd = dn2 ? ld4(wcb + (i + 1) * W + j0) : Z0;

        do_row<PASS, COMBINE>(zu, zc, zd, wcu, wcm, wv,
                              zsrc, pb, coef, wrb, o1, o2, pprev, aprev,
                              gi, lane, j0, acc);
        do_row<PASS, COMBINE>(zc, zd, ze, wcm, wcd, wv2,
                              zsrc, pb, coef, wrb, o1, o2, pprev, aprev,
                              gi + W, lane, j0, acc);
        zu = zd; zc = ze;
    }
    if (i < i1) {
        const bool up = (i > 0), dn = (i < H - 1);
        zd = dn ? ldz<COMBINE>(zsrc, pb, coef, gi + W) : Z0;
        float4 wv  = ld4(wrb + gi);
        float4 wcu = up ? ld4(wcb + (i - 1) * W + j0) : Z0;
        float4 wcd = dn ? ld4(wcb + i * W + j0) : Z0;
        do_row<PASS, COMBINE>(zu, zc, zd, wcu, wcd, wv,
                              zsrc, pb, coef, wrb, o1, o2, pprev, aprev,
                              gi, lane, j0, acc);
    }
}

// Per-group (128-thread) reduce; one atomicAdd per group per covered batch.
__device__ __forceinline__ void reduce_grp_atomic(float a0, float a1, int grp,
                                                  float* dst0, float* dst1)
{
    __shared__ float sm[2][3][4];
    #pragma unroll
    for (int o = 16; o; o >>= 1) {
        a0 += __shfl_down_sync(0xffffffffu, a0, o);
        a1 += __shfl_down_sync(0xffffffffu, a1, o);
    }
    int wg = (threadIdx.x >> 5) & 3;
    int lane = threadIdx.x & 31;
    if (lane == 0) { sm[0][grp][wg] = a0; sm[1][grp][wg] = a1; }
    __syncthreads();
    if (wg == 0 && lane == 0) {
        float t0 = sm[0][grp][0] + sm[0][grp][1] + sm[0][grp][2] + sm[0][grp][3];
        atomicAdd(dst0, t0);
        if (dst1) {
            float t1 = sm[1][grp][0] + sm[1][grp][1] + sm[1][grp][2] + sm[1][grp][3];
            atomicAdd(dst1, t1);
        }
    }
    __syncthreads();
}

// Iterate batch-aligned segments of batch-row range [q0,q1): calls f(b, i0, i1).
template<typename F>
__device__ __forceinline__ void for_segs(int q0, int q1, F f)
{
    int a = q0;
    while (a < q1) {
        int b = a >> 9;
        int send = q1 < ((b + 1) << 9) ? q1 : ((b + 1) << 9);
        f(b, a & 511, (a & 511) + (send - a));
        a = send;
    }
}

extern "C" __global__ void __launch_bounds__(TPB, 3)
cg_persistent(const float* __restrict__ Bin, const float* __restrict__ wc,
              const float* __restrict__ wr, float* __restrict__ x, int G)
{
    unsigned int gen = g_bar_phase;   // survives graph replays
    const int bi = blockIdx.x;
    const int r0 = (int)(((long long)bi * BROW) / G);
    const int r1 = (int)(((long long)(bi + 1) * BROW) / G);
    const int b0 = r0 >> 9;
    const int grp = threadIdx.x >> 7;           // channel 0..2
    const int j0 = (threadIdx.x & 127) << 2;
    const int lane = threadIdx.x & 31;
    const bool has2 = ((r1 - 1) >> 9) > b0;
    const int sA = (b0 * CH + grp) * 8;
    const int sB = ((b0 + 1) * CH + grp) * 8;

    // Phase Z: zero scalar slots + build padded row-weight buffer
    if (bi == 0) {
        for (int t = threadIdx.x; t < 3 * NS * 8; t += TPB) {
            (&g_pAp[0][0])[t] = 0.f;
            (&g_rr[0][0])[t] = 0.f;
        }
    }
    for (int t = bi * TPB + threadIdx.x; t < WPTOT; t += G * TPB) {
        int b = t >> 18;
        int rem = t & (SYS - 1);
        int i = rem >> 9, j = rem & 511;
        g_wrp[t] = (j < 511) ? wr[b * WRN + i * 511 + j] : 0.f;
    }
    grid_barrier(G, gen);

    // Setup: x = B; r = B - A*B; rr0 -> slot 0
    {
        float a0 = 0.f, a1 = 0.f;
        for_segs(r0, r1, [&](int b, int i0, int i1) {
            int s = b * CH + grp;
            float acc = 0.f;
            sweep_seg<0, false>(Bin + s * SYS, (const float*)0, 0.f,
                                wc + b * WCN, g_wrp + b * SYS,
                                g_r + s * SYS, x + s * SYS, (const float*)0, 0.f,
                                i0, i1, j0, lane, acc);
            if (b == b0) a0 += acc; else a1 += acc;
        });
        reduce_grp_atomic(a0, a1, grp, &g_rr[0][sA], has2 ? &g_rr[0][sB] : (float*)0);
    }
    grid_barrier(G, gen);

    float aprevA = 0.f, aprevB = 0.f;   // alpha_{it} stashed after each pass2
    int klast = MAXIT - 1;

    for (int it = 0; it < MAXIT; ++it) {
        const int cur = it % 3, prv = (it + 2) % 3, nxt = (it + 1) % 3;
        float* __restrict__ pnew = g_pbuf[it % 3];
        const float* __restrict__ pold = g_pbuf[(it + 2) % 3];

        // Pass 1: p = r + beta*p_old formed on load; store p; pAp dot
        {
            float bA = 0.f, bB = 0.f;
            if (it > 0) {
                bA = nan0(g_rr[cur][sA] / g_rr[prv][sA]);
                if (has2) bB = nan0(g_rr[cur][sB] / g_rr[prv][sB]);
            }
            float a0 = 0.f, a1 = 0.f;
            for_segs(r0, r1, [&](int b, int i0, int i1) {
                int s = b * CH + grp;
                float acc = 0.f;
                if (it == 0) {
                    sweep_seg<1, false>(g_r + s * SYS, (const float*)0, 0.f,
                                        wc + b * WCN, g_wrp + b * SYS,
                                        pnew + s * SYS, (float*)0, (const float*)0, 0.f,
                                        i0, i1, j0, lane, acc);
                } else {
                    float beta = (b == b0) ? bA : bB;
                    sweep_seg<1, true>(g_r + s * SYS, pold + s * SYS, beta,
                                       wc + b * WCN, g_wrp + b * SYS,
                                       pnew + s * SYS, (float*)0, (const float*)0, 0.f,
                                       i0, i1, j0, lane, acc);
                }
                if (b == b0) a0 += acc; else a1 += acc;
            });
            reduce_grp_atomic(a0, a1, grp, &g_pAp[cur][sA], has2 ? &g_pAp[cur][sB] : (float*)0);
            if (bi == 0) {
                for (int t = threadIdx.x; t < NS * 8; t += TPB) g_rr[nxt][t] = 0.f;
            }
        }
        grid_barrier(G, gen);

        // Pass 2: recompute Ap from p; r -= a*Ap; rr dot.
        // Odd it: also x += aprev*p_{it-1} + a*p_it (paired x update).
        {
            float aA = nan0(g_rr[cur][sA] / g_pAp[cur][sA]);
            float aB = has2 ? nan0(g_rr[cur][sB] / g_pAp[cur][sB]) : 0.f;
            const bool xup = (it & 1);
            float a0 = 0.f, a1 = 0.f;
            for_segs(r0, r1, [&](int b, int i0, int i1) {
                int s = b * CH + grp;
                float alpha = (b == b0) ? aA : aB;
                float aprev = (b == b0) ? aprevA : aprevB;
                float acc = 0.f;
                if (xup) {
                    sweep_seg<3, false>(pnew + s * SYS, (const float*)0, alpha,
                                        wc + b * WCN, g_wrp + b * SYS,
                                        g_r + s * SYS, x + s * SYS,
                                        pold + s * SYS, aprev,
                                        i0, i1, j0, lane, acc);
                } else {
                    sweep_seg<2, false>(pnew + s * SYS, (const float*)0, alpha,
                                        wc + b * WCN, g_wrp + b * SYS,
                                        g_r + s * SYS, x + s * SYS,
                                        (const float*)0, 0.f,
                                        i0, i1, j0, lane, acc);
                }
                if (b == b0) a0 += acc; else a1 += acc;
            });
            reduce_grp_atomic(a0, a1, grp, &g_rr[nxt][sA], has2 ? &g_rr[nxt][sB] : (float*)0);
            if (bi == 0) {
                for (int t = threadIdx.x; t < NS * 8; t += TPB) g_pAp[nxt][t] = 0.f;
            }
            aprevA = aA; aprevB = aB;
        }
        grid_barrier(G, gen);

        // Convergence (uniform across blocks)
        __shared__ int s_done;
        if (threadIdx.x == 0) {
            float tot = 0.f;
            for (int s = 0; s < NS; ++s) tot += g_rr[nxt][s * 8];
            s_done = (tot < EPS_F) ? 1 : 0;
        }
        __syncthreads();
        if (s_done) { klast = it; break; }
    }

    // Cleanup: if the last completed iteration was even, its x term is pending.
    // Own band only (no cross-block deps), pointwise x += alpha_klast * p_klast.
    if ((klast & 1) == 0) {
        const float* __restrict__ pl = g_pbuf[klast % 3];
        for_segs(r0, r1, [&](int b, int i0, int i1) {
            int s = b * CH + grp;
            float a = (b == b0) ? aprevA : aprevB;
            float* xx = x + s * SYS;
            const float* pp = pl + s * SYS;
            int gi = i0 * W + j0;
            for (int i = i0; i < i1; ++i, gi += W) {
                float4 xv = ld4(xx + gi);
                float4 pv = ld4(pp + gi);
                xv.x += a * pv.x; xv.y += a * pv.y;
                xv.z += a * pv.z; xv.w += a * pv.w;
                st4(xx + gi, xv);
            }
        });
    }
}

extern "C" void kernel_launch(void* const* d_in, const int* in_sizes, int n_in,
                              void* d_out, int out_size)
{
    static int G = 0;
    if (G == 0) {
        int dev = 0;
        cudaGetDevice(&dev);
        int sms = 0;
        cudaDeviceGetAttribute(&sms, cudaDevAttrMultiProcessorCount, dev);
        int occ = 0;
        cudaOccupancyMaxActiveBlocksPerMultiprocessor(&occ, cg_persistent, TPB, 0);
        if (occ < 1) occ = 1;
        G = sms * occ;
        if (G > BROW) G = BROW;
    }
    cg_persistent<<<G, TPB>>>((const float*)d_in[0], (const float*)d_in[1],
                              (const float*)d_in[2], (float*)d_out, G);
}